// round 6
// baseline (speedup 1.0000x reference)
#include <cuda_runtime.h>
#include <cstdint>

// Problem constants
#define NPTS   65536      // B*S = 4*16384
#define C      64         // IN_C == OUT_C
#define KNB    16         // neighbors
#define PPB    4          // points per block
#define ROWS   64         // PPB*KNB neighbor rows per block
#define AS     68         // padded row stride (odd float4 stride -> conflict-free)
#define HS     20         // padded row stride for H buffer
#define THREADS 256

// ---------------- constant-bank weights (warp-uniform access -> LDCU path) --------------
__constant__ float cWkN[4096];   // [c][o], NEGATED Wk
__constant__ float cWv[4096];    // [c][o]
__constant__ float cWpe2[4096];  // [c][o]
__constant__ float cWa1[1024];   // [c][m]
__constant__ float cWa2[1024];   // [m][o]
__constant__ float cWpe1[192];   // [d][o]

// per-lane-accessed weights stay in global (L1-resident)
__device__ __align__(16) float gWq_t[4096];    // [c][o]
__device__ __align__(16) float gWproj_t[4096]; // [c][o]

__global__ void prep_kernel(const float* __restrict__ Wq, const float* __restrict__ Wk,
                            const float* __restrict__ Wv, const float* __restrict__ Wpe1,
                            const float* __restrict__ Wpe2, const float* __restrict__ Wa1,
                            const float* __restrict__ Wa2, const float* __restrict__ Wproj,
                            float* dWkN, float* dWv, float* dWpe2,
                            float* dWa1, float* dWa2, float* dWpe1) {
    int t = blockIdx.x * blockDim.x + threadIdx.x;
    if (t < 4096) {
        int o = t >> 6, c = t & 63;        // row-major [o][c] source
        gWq_t  [c*64 + o] =  Wq[t];
        gWproj_t[c*64 + o] = Wproj[t];
        dWkN [c*64 + o] = -Wk[t];          // negated: s = q + pe + (A @ -Wk)
        dWv  [c*64 + o] =  Wv[t];
        dWpe2[c*64 + o] =  Wpe2[t];
    }
    if (t < 1024) {
        int m = t >> 6, c = t & 63;        // Wa1 is [16][64]
        dWa1[c*16 + m] = Wa1[t];
        int o = t >> 4, mm = t & 15;       // Wa2 is [64][16]
        dWa2[mm*64 + o] = Wa2[t];
    }
    if (t < 192) {
        int o = t / 3, d = t - o*3;        // Wpe1 is [64][3]
        dWpe1[d*64 + o] = Wpe1[t];
    }
}

// ---------------- f32x2 packed math helpers ----------------
__device__ __forceinline__ void fma2(uint64_t& d, uint64_t a, uint64_t b) {
    asm("fma.rn.f32x2 %0, %1, %2, %0;" : "+l"(d) : "l"(a), "l"(b));
}
__device__ __forceinline__ uint64_t add2(uint64_t a, uint64_t b) {
    uint64_t d; asm("add.rn.f32x2 %0, %1, %2;" : "=l"(d) : "l"(a), "l"(b)); return d;
}
__device__ __forceinline__ uint64_t pack2(float x, float y) {
    uint64_t d; asm("mov.b64 %0, {%1, %2};" : "=l"(d) : "f"(x), "f"(y)); return d;
}
__device__ __forceinline__ uint64_t dup2(float x) { return pack2(x, x); }
__device__ __forceinline__ void unpack2(uint64_t v, float& x, float& y) {
    asm("mov.b64 {%0, %1}, %2;" : "=f"(x), "=f"(y) : "l"(v));
}

// ---------------- templated GEMM stages (O0/M0 compile-time -> uniform const addrs) -----
// Warp tile: 32 rows (r = 32*rh + lane) x 16 cols (O0..O0+15); thread = 1 row x 16 cols.
template<int W4>
__device__ __forceinline__ void gemm_stages(float* sNF, float* sPE, float* sH,
                                            const float* sREL, const float* sQ,
                                            int rh, int l) {
    constexpr int O0 = W4 * 16;
    constexpr int M0 = W4 * 4;
    const int r = rh*32 + l;
    float* rowPE = sPE + r*AS;
    float* rowNF = sNF + r*AS;

    // ---- B: pe_raw = relu(rel @ Wpe1^T) -> sPE[r][O0..O0+15] ----
    {
        uint64_t acc[8];
#pragma unroll
        for (int j = 0; j < 8; ++j) acc[j] = 0ULL;
#pragma unroll
        for (int d = 0; d < 3; ++d) {
            uint64_t a = dup2(sREL[r*4 + d]);
#pragma unroll
            for (int j = 0; j < 4; ++j) {
                ulonglong2 wp = *reinterpret_cast<const ulonglong2*>(cWpe1 + d*64 + O0 + 4*j);
                fma2(acc[2*j],   a, wp.x);
                fma2(acc[2*j+1], a, wp.y);
            }
        }
#pragma unroll
        for (int j = 0; j < 8; ++j) {
            float x, y; unpack2(acc[j], x, y);
            acc[j] = pack2(fmaxf(x, 0.f), fmaxf(y, 0.f));
        }
#pragma unroll
        for (int j = 0; j < 4; ++j)
            *reinterpret_cast<ulonglong2*>(rowPE + O0 + 4*j) = make_ulonglong2(acc[2*j], acc[2*j+1]);
    }
    __syncthreads();   // (1) pe_raw complete; sQ (written pre-switch) also visible

    // ---- C: pe = pe_raw @ Wpe2^T  (kept in registers pc[]; never stored) ----
    uint64_t pc[8];
#pragma unroll
    for (int j = 0; j < 8; ++j) pc[j] = 0ULL;
#pragma unroll 2
    for (int c = 0; c < 64; c += 4) {
        float4 A = *reinterpret_cast<const float4*>(rowPE + c);
        float av4[4] = {A.x, A.y, A.z, A.w};
#pragma unroll
        for (int u = 0; u < 4; ++u) {
            uint64_t a = dup2(av4[u]);
#pragma unroll
            for (int j = 0; j < 4; ++j) {
                ulonglong2 wp = *reinterpret_cast<const ulonglong2*>(cWpe2 + (c+u)*64 + O0 + 4*j);
                fma2(pc[2*j],   a, wp.x);
                fma2(pc[2*j+1], a, wp.y);
            }
        }
    }
    __syncthreads();   // (2) all reads of pe_raw done -> sPE writable by D

    // ---- D: kk & v in one A pass; s = q - kk + pe -> sPE ; vpe = v + pe -> sNF ----
    {
        uint64_t ak[8], av_[8];
        const int p = r >> 4;
#pragma unroll
        for (int j = 0; j < 8; ++j) {
            uint64_t q = *reinterpret_cast<const uint64_t*>(sQ + p*C + O0 + 2*j);
            ak[j]  = add2(q, pc[j]);
            av_[j] = pc[j];
        }
#pragma unroll 2
        for (int c = 0; c < 64; c += 4) {
            float4 A = *reinterpret_cast<const float4*>(rowNF + c);
            float av4[4] = {A.x, A.y, A.z, A.w};
#pragma unroll
            for (int u = 0; u < 4; ++u) {
                uint64_t a = dup2(av4[u]);
#pragma unroll
                for (int j = 0; j < 4; ++j) {
                    ulonglong2 wk = *reinterpret_cast<const ulonglong2*>(cWkN + (c+u)*64 + O0 + 4*j);
                    fma2(ak[2*j],   a, wk.x);
                    fma2(ak[2*j+1], a, wk.y);
                }
#pragma unroll
                for (int j = 0; j < 4; ++j) {
                    ulonglong2 wv = *reinterpret_cast<const ulonglong2*>(cWv + (c+u)*64 + O0 + 4*j);
                    fma2(av_[2*j],   a, wv.x);
                    fma2(av_[2*j+1], a, wv.y);
                }
            }
        }
        __syncthreads();   // (3) all reads of neigh_feat done -> sNF writable
#pragma unroll
        for (int j = 0; j < 4; ++j) {
            *reinterpret_cast<ulonglong2*>(rowPE + O0 + 4*j) = make_ulonglong2(ak[2*j],  ak[2*j+1]);
            *reinterpret_cast<ulonglong2*>(rowNF + O0 + 4*j) = make_ulonglong2(av_[2*j], av_[2*j+1]);
        }
    }
    __syncthreads();   // (4) s and vpe visible

    // ---- F: h[r][M0..M0+3] = relu(s[r] @ Wa1^T) ----
    {
        uint64_t h0 = 0ULL, h1 = 0ULL;
#pragma unroll 4
        for (int c = 0; c < 64; c += 4) {
            float4 A = *reinterpret_cast<const float4*>(rowPE + c);
            float av4[4] = {A.x, A.y, A.z, A.w};
#pragma unroll
            for (int u = 0; u < 4; ++u) {
                uint64_t a = dup2(av4[u]);
                ulonglong2 wp = *reinterpret_cast<const ulonglong2*>(cWa1 + (c+u)*16 + M0);
                fma2(h0, a, wp.x);
                fma2(h1, a, wp.y);
            }
        }
        float x, y;
        unpack2(h0, x, y); h0 = pack2(fmaxf(x, 0.f), fmaxf(y, 0.f));
        unpack2(h1, x, y); h1 = pack2(fmaxf(x, 0.f), fmaxf(y, 0.f));
        *reinterpret_cast<ulonglong2*>(sH + r*HS + M0) = make_ulonglong2(h0, h1);
    }
    __syncthreads();   // (5) h complete; all reads of s done

    // ---- G: logits = h @ Wa2^T -> sPE (overwrites s) ----
    {
        uint64_t g[8];
#pragma unroll
        for (int j = 0; j < 8; ++j) g[j] = 0ULL;
#pragma unroll
        for (int m = 0; m < 16; m += 4) {
            float4 H = *reinterpret_cast<const float4*>(sH + r*HS + m);
            float hv[4] = {H.x, H.y, H.z, H.w};
#pragma unroll
            for (int u = 0; u < 4; ++u) {
                uint64_t a = dup2(hv[u]);
#pragma unroll
                for (int j = 0; j < 4; ++j) {
                    ulonglong2 wp = *reinterpret_cast<const ulonglong2*>(cWa2 + (m+u)*64 + O0 + 4*j);
                    fma2(g[2*j],   a, wp.x);
                    fma2(g[2*j+1], a, wp.y);
                }
            }
        }
#pragma unroll
        for (int j = 0; j < 4; ++j)
            *reinterpret_cast<ulonglong2*>(rowPE + O0 + 4*j) = make_ulonglong2(g[2*j], g[2*j+1]);
    }
}

// ---------------- main fused kernel ----------------
__global__ void __launch_bounds__(THREADS, 3)
lab_kernel(const float* __restrict__ cxyz, const float* __restrict__ cfeat,
           const float* __restrict__ nxyz, const float* __restrict__ nfeat,
           const float* __restrict__ lnw,  const float* __restrict__ lnb,
           float* __restrict__ out) {
    extern __shared__ float sm[];
    float* sNF  = sm;               // [64][AS]  neigh_feat -> later vpe
    float* sPE  = sNF  + 4352;      // [64][AS]  pe_raw -> s -> logits
    float* sH   = sPE  + 4352;      // [64][HS]  h
    float* sREL = sH   + 1280;      // [64][4]   relative xyz
    float* sCF  = sREL + 256;       // [4][64]   center_feat
    float* sQ   = sCF  + 256;       // [4][64]   q -> later y (pre-LN)
    float* sO   = sQ   + 256;       // [4][64]   attention output
    // total 11008 floats = 44032 B

    const int tid = threadIdx.x;
    const int p0  = blockIdx.x * PPB;
    const int w   = tid >> 5;
    const int l   = tid & 31;
    const int rh  = w >> 2;          // row half

    // ---- Stage A: load inputs into smem ----
    {
        const float4* nf4 = reinterpret_cast<const float4*>(nfeat + (size_t)p0*KNB*C);
#pragma unroll
        for (int j = tid; j < ROWS*C/4; j += THREADS) {
            float4 v = __ldcs(nf4 + j);
            int e = j*4; int r = e >> 6; int c = e & 63;
            *reinterpret_cast<float4*>(sNF + r*AS + c) = v;
        }
        if (tid < PPB*C/4) {
            float4 v = __ldcs(reinterpret_cast<const float4*>(cfeat + (size_t)p0*C) + tid);
            int e = tid*4; int i = e >> 6; int c = e & 63;
            *reinterpret_cast<float4*>(sCF + i*C + c) = v;
        }
        if (tid < ROWS) {
            int r = tid, i = r >> 4;
            float cx0 = __ldcs(cxyz + (p0+i)*3 + 0);
            float cx1 = __ldcs(cxyz + (p0+i)*3 + 1);
            float cx2 = __ldcs(cxyz + (p0+i)*3 + 2);
            int nb = (p0*KNB + r)*3;
            sREL[r*4+0] = __ldcs(nxyz + nb + 0) - cx0;
            sREL[r*4+1] = __ldcs(nxyz + nb + 1) - cx1;
            sREL[r*4+2] = __ldcs(nxyz + nb + 2) - cx2;
        }
    }
    __syncthreads();

    // ---- q = cf @ Wq^T -> sQ (visible to all at template sync (1)) ----
    {
        int i = tid >> 6, o = tid & 63;
        float acc = 0.f;
#pragma unroll 8
        for (int c = 0; c < 64; ++c) acc = fmaf(sCF[i*C + c], __ldg(gWq_t + c*64 + o), acc);
        sQ[i*C + o] = acc;
    }

    // ---- GEMM-heavy stages, 4-way specialized on column block ----
    switch (w & 3) {
        case 0: gemm_stages<0>(sNF, sPE, sH, sREL, sQ, rh, l); break;
        case 1: gemm_stages<1>(sNF, sPE, sH, sREL, sQ, rh, l); break;
        case 2: gemm_stages<2>(sNF, sPE, sH, sREL, sQ, rh, l); break;
        default: gemm_stages<3>(sNF, sPE, sH, sREL, sQ, rh, l); break;
    }
    __syncthreads();   // logits + vpe visible

    // ---- Stage H: softmax over K + weighted sum of vpe -> sO ----
    {
        int i = tid >> 6, o = tid & 63;
        int rbase = i * KNB;
        float wv[KNB];
        float mx = -1e30f;
#pragma unroll
        for (int k = 0; k < KNB; ++k) {
            wv[k] = sPE[(rbase+k)*AS + o];
            mx = fmaxf(mx, wv[k]);
        }
        float sum = 0.f;
#pragma unroll
        for (int k = 0; k < KNB; ++k) { wv[k] = __expf(wv[k] - mx); sum += wv[k]; }
        float inv = 1.f / sum;
        float acc = 0.f;
#pragma unroll
        for (int k = 0; k < KNB; ++k) acc = fmaf(wv[k], sNF[(rbase+k)*AS + o], acc);
        sO[i*C + o] = acc * inv;
    }
    __syncthreads();

    // ---- Stage I: proj + residual -> sQ (reused as y) ----
    {
        int i = tid >> 6, o = tid & 63;
        float acc = sCF[i*C + o];
#pragma unroll 8
        for (int c = 0; c < 64; ++c) acc = fmaf(sO[i*C + c], __ldg(gWproj_t + c*64 + o), acc);
        sQ[i*C + o] = acc;
    }
    __syncthreads();

    // ---- Stage J: LayerNorm + global store ----
    {
        int wp = tid >> 5, lid = tid & 31;
        if (wp < PPB) {
            float y0 = sQ[wp*C + lid];
            float y1 = sQ[wp*C + lid + 32];
            float s  = y0 + y1;
            float s2 = y0*y0 + y1*y1;
#pragma unroll
            for (int off = 16; off; off >>= 1) {
                s  += __shfl_xor_sync(0xFFFFFFFFu, s,  off);
                s2 += __shfl_xor_sync(0xFFFFFFFFu, s2, off);
            }
            float mu  = s * (1.f/64.f);
            float var = s2 * (1.f/64.f) - mu*mu;
            float rs  = rsqrtf(var + 1e-5f);
            int g = p0 + wp;
            out[(size_t)g*C + lid]      = (y0 - mu) * rs * lnw[lid]      + lnb[lid];
            out[(size_t)g*C + lid + 32] = (y1 - mu) * rs * lnw[lid + 32] + lnb[lid + 32];
        }
    }
}

// ---------------- launch ----------------
extern "C" void kernel_launch(void* const* d_in, const int* in_sizes, int n_in,
                              void* d_out, int out_size) {
    (void)in_sizes; (void)n_in; (void)out_size;
    const float* cxyz  = (const float*)d_in[0];
    const float* cfeat = (const float*)d_in[1];
    const float* nxyz  = (const float*)d_in[2];
    const float* nfeat = (const float*)d_in[3];
    const float* Wq    = (const float*)d_in[4];
    const float* Wk    = (const float*)d_in[5];
    const float* Wv    = (const float*)d_in[6];
    const float* Wpe1  = (const float*)d_in[7];
    const float* Wpe2  = (const float*)d_in[8];
    const float* Wa1   = (const float*)d_in[9];
    const float* Wa2   = (const float*)d_in[10];
    const float* Wproj = (const float*)d_in[11];
    const float* lnw   = (const float*)d_in[12];
    const float* lnb   = (const float*)d_in[13];

    // writable aliases of the constant-bank symbols (query only; no allocation)
    float *dWkN, *dWv, *dWpe2, *dWa1, *dWa2, *dWpe1;
    cudaGetSymbolAddress((void**)&dWkN,  cWkN);
    cudaGetSymbolAddress((void**)&dWv,   cWv);
    cudaGetSymbolAddress((void**)&dWpe2, cWpe2);
    cudaGetSymbolAddress((void**)&dWa1,  cWa1);
    cudaGetSymbolAddress((void**)&dWa2,  cWa2);
    cudaGetSymbolAddress((void**)&dWpe1, cWpe1);

    prep_kernel<<<16, 256>>>(Wq, Wk, Wv, Wpe1, Wpe2, Wa1, Wa2, Wproj,
                             dWkN, dWv, dWpe2, dWa1, dWa2, dWpe1);

    size_t smem = 11008 * sizeof(float);   // 44 KB -> 3 blocks/SM with regs<=84
    cudaFuncSetAttribute(lab_kernel, cudaFuncAttributeMaxDynamicSharedMemorySize, (int)smem);
    lab_kernel<<<NPTS/PPB, THREADS, smem>>>(cxyz, cfeat, nxyz, nfeat, lnw, lnb, (float*)d_out);
}

// round 8
// speedup vs baseline: 3.1020x; 3.1020x over previous
#include <cuda_runtime.h>
#include <cstdint>

// Problem constants
#define NPTS   65536      // B*S = 4*16384
#define C      64         // IN_C == OUT_C
#define KNB    16         // neighbors
#define PPB    4          // points per block
#define ROWS   64         // PPB*KNB neighbor rows per block
#define AS     68         // padded row stride
#define HS     20         // padded row stride for H buffer
#define THREADS 256

// ---------------- device-global weight scratch (no allocs) ----------------
__device__ __align__(16) float gWq_t[4096];     // [c][o]
__device__ __align__(16) float gWproj_t[4096];  // [c][o]
__device__ __align__(16) float gWkN[4096];      // [c][o], NEGATED Wk
__device__ __align__(16) float gWv[4096];       // [c][o]
__device__ __align__(16) float gPe2p[4096];     // packed pairs: u64[kp*64+o] = {W[2kp][o], W[2kp+1][o]}
__device__ __align__(16) float gWa1p[1024];     // packed: u64[kp*16+m]
__device__ __align__(16) float gWa2p[1024];     // packed: u64[mp*64+o]
__device__ __align__(16) float gWpe1[192];      // [d][o]

__global__ void prep_kernel(const float* __restrict__ Wq, const float* __restrict__ Wk,
                            const float* __restrict__ Wv, const float* __restrict__ Wpe1,
                            const float* __restrict__ Wpe2, const float* __restrict__ Wa1,
                            const float* __restrict__ Wa2, const float* __restrict__ Wproj) {
    int t = blockIdx.x * blockDim.x + threadIdx.x;
    if (t < 4096) {
        int o = t >> 6, c = t & 63;        // source row-major [o][c]
        gWq_t  [c*64 + o] =  Wq[t];
        gWproj_t[c*64 + o] = Wproj[t];
        gWkN   [c*64 + o] = -Wk[t];        // negated: s = q + pe + (A @ -Wk)
        gWv    [c*64 + o] =  Wv[t];
        gPe2p[(c>>1)*128 + o*2 + (c&1)] = Wpe2[t];
    }
    if (t < 1024) {
        int m = t >> 6, c = t & 63;        // Wa1 is [16][64]
        gWa1p[(c>>1)*32 + m*2 + (c&1)] = Wa1[t];
        int o = t >> 4, mm = t & 15;       // Wa2 is [64][16]
        gWa2p[(mm>>1)*128 + o*2 + (mm&1)] = Wa2[t];
    }
    if (t < 192) {
        int o = t / 3, d = t - o*3;        // Wpe1 is [64][3]
        gWpe1[d*64 + o] = Wpe1[t];
    }
}

// ---------------- f32x2 packed math helpers ----------------
__device__ __forceinline__ void fma2(uint64_t& d, uint64_t a, uint64_t b) {
    asm("fma.rn.f32x2 %0, %1, %2, %0;" : "+l"(d) : "l"(a), "l"(b));
}
__device__ __forceinline__ uint64_t add2(uint64_t a, uint64_t b) {
    uint64_t d; asm("add.rn.f32x2 %0, %1, %2;" : "=l"(d) : "l"(a), "l"(b)); return d;
}
__device__ __forceinline__ uint64_t pack2(float x, float y) {
    uint64_t d; asm("mov.b64 %0, {%1, %2};" : "=l"(d) : "f"(x), "f"(y)); return d;
}
__device__ __forceinline__ uint64_t dup2(float x) { return pack2(x, x); }
__device__ __forceinline__ void unpack2(uint64_t v, float& x, float& y) {
    asm("mov.b64 {%0, %1}, %2;" : "=f"(x), "=f"(y) : "l"(v));
}
__device__ __forceinline__ float hsum2(uint64_t v) {
    float x, y; unpack2(v, x, y); return x + y;
}

// ---------------- main fused kernel ----------------
__global__ void __launch_bounds__(THREADS, 2)
lab_kernel(const float* __restrict__ cxyz, const float* __restrict__ cfeat,
           const float* __restrict__ nxyz, const float* __restrict__ nfeat,
           const float* __restrict__ lnw,  const float* __restrict__ lnb,
           float* __restrict__ out) {
    extern __shared__ float sm[];
    float* sNF   = sm;                 // [64][AS] neigh_feat -> later vpe
    float* sPE   = sNF  + 4352;        // [64][AS] pe_raw -> s -> logits
    float* sH    = sPE  + 4352;        // [64][HS] h
    float* sREL  = sH   + 1280;        // [64][4]  relative xyz
    float* sCF   = sREL + 256;         // [4][64]  center_feat
    float* sQ    = sCF  + 256;         // [4][64]  q -> later y (pre-LN)
    float* sO    = sQ   + 256;         // [4][64]  attention output
    float* sWk   = sO   + 256;         // [64][64] -Wk^T (scalar layout)
    float* sWv   = sWk  + 4096;        // [64][64] Wv^T
    float* sPe2  = sWv  + 4096;        // packed pairs (4096 floats)
    float* sWa1p = sPe2 + 4096;        // packed (1024)
    float* sWa2p = sWa1p+ 1024;        // packed (1024)
    float* sWpe1 = sWa2p+ 1024;        // [3][64]
    // total 25536 floats = 102144 B -> 2 blocks/SM

    const int tid = threadIdx.x;
    const int p0  = blockIdx.x * PPB;
    const int w   = tid >> 5;
    const int l   = tid & 31;
    const int rg  = l >> 2;            // 0..7
    const int cg  = l & 3;             // 0..3
    const int rowbase = (w >> 2) * 32; // row half
    const int O0      = (w & 3) * 16;  // col block
    const int colbase = O0 + cg * 4;   // this thread's 4 cols
    int r_[4];
#pragma unroll
    for (int j = 0; j < 4; ++j) r_[j] = rowbase + rg + 8*j;   // interleaved rows (dedup + CF)

    // ---- Stage A: load inputs + stage weights into smem ----
    {
        const float4* nf4 = reinterpret_cast<const float4*>(nfeat + (size_t)p0*KNB*C);
#pragma unroll
        for (int j = tid; j < ROWS*C/4; j += THREADS) {
            float4 v = __ldcs(nf4 + j);
            int e = j*4; int r = e >> 6; int c = e & 63;
            *reinterpret_cast<float4*>(sNF + r*AS + c) = v;
        }
#pragma unroll
        for (int j = tid; j < 1024; j += THREADS) {
            reinterpret_cast<float4*>(sWk)[j]  = reinterpret_cast<const float4*>(gWkN)[j];
            reinterpret_cast<float4*>(sWv)[j]  = reinterpret_cast<const float4*>(gWv)[j];
            reinterpret_cast<float4*>(sPe2)[j] = reinterpret_cast<const float4*>(gPe2p)[j];
        }
        if (tid < 256) {
            reinterpret_cast<float4*>(sWa1p)[tid] = reinterpret_cast<const float4*>(gWa1p)[tid];
            reinterpret_cast<float4*>(sWa2p)[tid] = reinterpret_cast<const float4*>(gWa2p)[tid];
        }
        if (tid < 48)
            reinterpret_cast<float4*>(sWpe1)[tid] = reinterpret_cast<const float4*>(gWpe1)[tid];
        if (tid < PPB*C/4) {
            float4 v = __ldcs(reinterpret_cast<const float4*>(cfeat + (size_t)p0*C) + tid);
            int e = tid*4; int i = e >> 6; int c = e & 63;
            *reinterpret_cast<float4*>(sCF + i*C + c) = v;
        }
        if (tid < ROWS) {
            int r = tid, i = r >> 4;
            float cx0 = __ldcs(cxyz + (p0+i)*3 + 0);
            float cx1 = __ldcs(cxyz + (p0+i)*3 + 1);
            float cx2 = __ldcs(cxyz + (p0+i)*3 + 2);
            int nb = (p0*KNB + r)*3;
            sREL[r*4+0] = __ldcs(nxyz + nb + 0) - cx0;
            sREL[r*4+1] = __ldcs(nxyz + nb + 1) - cx1;
            sREL[r*4+2] = __ldcs(nxyz + nb + 2) - cx2;
        }
    }
    __syncthreads();

    // ---- q = cf @ Wq^T -> sQ ----
    {
        int i = tid >> 6, o = tid & 63;
        float acc = 0.f;
#pragma unroll 8
        for (int c = 0; c < 64; ++c) acc = fmaf(sCF[i*C + c], __ldg(gWq_t + c*64 + o), acc);
        sQ[i*C + o] = acc;
    }

    // ---- Stage B: pe_raw = relu(rel @ Wpe1^T) -> sPE (4 rows x 4 cols / thread) ----
    {
        uint64_t b0[4], b1[4];
#pragma unroll
        for (int j = 0; j < 4; ++j) { b0[j] = 0ULL; b1[j] = 0ULL; }
#pragma unroll
        for (int d = 0; d < 3; ++d) {
            ulonglong2 wp = *reinterpret_cast<const ulonglong2*>(sWpe1 + d*64 + colbase);
#pragma unroll
            for (int j = 0; j < 4; ++j) {
                uint64_t a = dup2(sREL[r_[j]*4 + d]);
                fma2(b0[j], a, wp.x);
                fma2(b1[j], a, wp.y);
            }
        }
#pragma unroll
        for (int j = 0; j < 4; ++j) {
            float x0,y0,x1,y1;
            unpack2(b0[j], x0, y0); unpack2(b1[j], x1, y1);
            float4 v = {fmaxf(x0,0.f), fmaxf(y0,0.f), fmaxf(x1,0.f), fmaxf(y1,0.f)};
            *reinterpret_cast<float4*>(sPE + r_[j]*AS + colbase) = v;
        }
    }
    __syncthreads();   // (1) pe_raw + q visible

    // ---- Stage C: pe = pe_raw @ Wpe2^T  (k-pair packed; kept in registers) ----
    float pe[4][4];
    {
        uint64_t pc[4][4];
#pragma unroll
        for (int j = 0; j < 4; ++j)
#pragma unroll
            for (int cl = 0; cl < 4; ++cl) pc[j][cl] = 0ULL;
#pragma unroll 4
        for (int c = 0; c < 64; c += 4) {
            ulonglong2 A[4];
#pragma unroll
            for (int j = 0; j < 4; ++j)
                A[j] = *reinterpret_cast<const ulonglong2*>(sPE + r_[j]*AS + c);
            const float* pw = sPe2 + (c>>1)*128 + colbase*2;
            ulonglong2 wA = *reinterpret_cast<const ulonglong2*>(pw);        // kp0 cols 0-1
            ulonglong2 wB = *reinterpret_cast<const ulonglong2*>(pw + 4);    // kp0 cols 2-3
            ulonglong2 wC = *reinterpret_cast<const ulonglong2*>(pw + 128);  // kp1 cols 0-1
            ulonglong2 wD = *reinterpret_cast<const ulonglong2*>(pw + 132);  // kp1 cols 2-3
#pragma unroll
            for (int j = 0; j < 4; ++j) {
                fma2(pc[j][0], A[j].x, wA.x); fma2(pc[j][1], A[j].x, wA.y);
                fma2(pc[j][2], A[j].x, wB.x); fma2(pc[j][3], A[j].x, wB.y);
                fma2(pc[j][0], A[j].y, wC.x); fma2(pc[j][1], A[j].y, wC.y);
                fma2(pc[j][2], A[j].y, wD.x); fma2(pc[j][3], A[j].y, wD.y);
            }
        }
#pragma unroll
        for (int j = 0; j < 4; ++j)
#pragma unroll
            for (int cl = 0; cl < 4; ++cl) pe[j][cl] = hsum2(pc[j][cl]);
    }
    // no barrier needed here: D's smem writes are fenced by the barrier inside D

    // ---- Stage D: kk & v one A pass; s = q - kk + pe -> sPE ; vpe = v + pe -> sNF ----
    {
        uint64_t ak[4][2], av[4][2];
        const int pbase = (w >> 2) * 2;
#pragma unroll
        for (int j = 0; j < 4; ++j) {
            int p = pbase + (j >> 1);
            uint64_t q0 = *reinterpret_cast<const uint64_t*>(sQ + p*C + colbase);
            uint64_t q1 = *reinterpret_cast<const uint64_t*>(sQ + p*C + colbase + 2);
            uint64_t pe01 = pack2(pe[j][0], pe[j][1]);
            uint64_t pe23 = pack2(pe[j][2], pe[j][3]);
            ak[j][0] = add2(q0, pe01); ak[j][1] = add2(q1, pe23);
            av[j][0] = pe01;           av[j][1] = pe23;
        }
#pragma unroll 4
        for (int c = 0; c < 64; c += 4) {
            float4 A[4];
#pragma unroll
            for (int j = 0; j < 4; ++j)
                A[j] = *reinterpret_cast<const float4*>(sNF + r_[j]*AS + c);
            float Av[4][4];
#pragma unroll
            for (int j = 0; j < 4; ++j) {
                Av[j][0]=A[j].x; Av[j][1]=A[j].y; Av[j][2]=A[j].z; Av[j][3]=A[j].w;
            }
#pragma unroll
            for (int u = 0; u < 4; ++u) {
                ulonglong2 wk = *reinterpret_cast<const ulonglong2*>(sWk + (c+u)*64 + colbase);
                ulonglong2 wv = *reinterpret_cast<const ulonglong2*>(sWv + (c+u)*64 + colbase);
#pragma unroll
                for (int j = 0; j < 4; ++j) {
                    uint64_t a = dup2(Av[j][u]);
                    fma2(ak[j][0], a, wk.x); fma2(ak[j][1], a, wk.y);
                    fma2(av[j][0], a, wv.x); fma2(av[j][1], a, wv.y);
                }
            }
        }
        __syncthreads();   // (3) all reads of sNF & pe_raw done -> buffers writable
#pragma unroll
        for (int j = 0; j < 4; ++j) {
            *reinterpret_cast<ulonglong2*>(sPE + r_[j]*AS + colbase) = make_ulonglong2(ak[j][0], ak[j][1]);
            *reinterpret_cast<ulonglong2*>(sNF + r_[j]*AS + colbase) = make_ulonglong2(av[j][0], av[j][1]);
        }
    }
    __syncthreads();   // (4) s and vpe visible

    // ---- Stage F: h = relu(s @ Wa1^T) (warp w -> rows 8w..8w+7; thread = 1 row x 4 mids) ----
    {
        const int frow  = 8*w + rg;
        const int mbase = cg*4;
        uint64_t h[4] = {0ULL, 0ULL, 0ULL, 0ULL};
#pragma unroll 4
        for (int c = 0; c < 64; c += 4) {
            ulonglong2 A = *reinterpret_cast<const ulonglong2*>(sPE + frow*AS + c);
            const float* pw = sWa1p + (c>>1)*32 + mbase*2;
            ulonglong2 wA = *reinterpret_cast<const ulonglong2*>(pw);       // kp0 mids 0-1
            ulonglong2 wB = *reinterpret_cast<const ulonglong2*>(pw + 4);   // kp0 mids 2-3
            ulonglong2 wC = *reinterpret_cast<const ulonglong2*>(pw + 32);  // kp1 mids 0-1
            ulonglong2 wD = *reinterpret_cast<const ulonglong2*>(pw + 36);  // kp1 mids 2-3
            fma2(h[0], A.x, wA.x); fma2(h[1], A.x, wA.y);
            fma2(h[2], A.x, wB.x); fma2(h[3], A.x, wB.y);
            fma2(h[0], A.y, wC.x); fma2(h[1], A.y, wC.y);
            fma2(h[2], A.y, wD.x); fma2(h[3], A.y, wD.y);
        }
        float4 hv = {fmaxf(hsum2(h[0]),0.f), fmaxf(hsum2(h[1]),0.f),
                     fmaxf(hsum2(h[2]),0.f), fmaxf(hsum2(h[3]),0.f)};
        *reinterpret_cast<float4*>(sH + frow*HS + mbase) = hv;
    }
    __syncthreads();   // (5) h complete; all reads of s done

    // ---- Stage G: logits = h @ Wa2^T -> sPE (m-pair packed; 4 rows x 4 cols / thread) ----
    {
        uint64_t g[4][4];
#pragma unroll
        for (int j = 0; j < 4; ++j)
#pragma unroll
            for (int cl = 0; cl < 4; ++cl) g[j][cl] = 0ULL;
#pragma unroll
        for (int m = 0; m < 16; m += 4) {
            ulonglong2 A[4];
#pragma unroll
            for (int j = 0; j < 4; ++j)
                A[j] = *reinterpret_cast<const ulonglong2*>(sH + r_[j]*HS + m);
            const float* pw = sWa2p + (m>>1)*128 + colbase*2;
            ulonglong2 wA = *reinterpret_cast<const ulonglong2*>(pw);
            ulonglong2 wB = *reinterpret_cast<const ulonglong2*>(pw + 4);
            ulonglong2 wC = *reinterpret_cast<const ulonglong2*>(pw + 128);
            ulonglong2 wD = *reinterpret_cast<const ulonglong2*>(pw + 132);
#pragma unroll
            for (int j = 0; j < 4; ++j) {
                fma2(g[j][0], A[j].x, wA.x); fma2(g[j][1], A[j].x, wA.y);
                fma2(g[j][2], A[j].x, wB.x); fma2(g[j][3], A[j].x, wB.y);
                fma2(g[j][0], A[j].y, wC.x); fma2(g[j][1], A[j].y, wC.y);
                fma2(g[j][2], A[j].y, wD.x); fma2(g[j][3], A[j].y, wD.y);
            }
        }
#pragma unroll
        for (int j = 0; j < 4; ++j) {
            float4 v = {hsum2(g[j][0]), hsum2(g[j][1]), hsum2(g[j][2]), hsum2(g[j][3])};
            *reinterpret_cast<float4*>(sPE + r_[j]*AS + colbase) = v;
        }
    }
    __syncthreads();   // (6) logits visible

    // ---- Stage H: softmax over K + weighted sum of vpe -> sO ----
    {
        int i = tid >> 6, o = tid & 63;
        int rbase = i * KNB;
        float wv[KNB];
        float mx = -1e30f;
#pragma unroll
        for (int k = 0; k < KNB; ++k) {
            wv[k] = sPE[(rbase+k)*AS + o];
            mx = fmaxf(mx, wv[k]);
        }
        float sum = 0.f;
#pragma unroll
        for (int k = 0; k < KNB; ++k) { wv[k] = __expf(wv[k] - mx); sum += wv[k]; }
        float inv = 1.f / sum;
        float acc = 0.f;
#pragma unroll
        for (int k = 0; k < KNB; ++k) acc = fmaf(wv[k], sNF[(rbase+k)*AS + o], acc);
        sO[i*C + o] = acc * inv;
    }
    __syncthreads();

    // ---- Stage I: proj + residual -> sQ (reused as y) ----
    {
        int i = tid >> 6, o = tid & 63;
        float acc = sCF[i*C + o];
#pragma unroll 8
        for (int c = 0; c < 64; ++c) acc = fmaf(sO[i*C + c], __ldg(gWproj_t + c*64 + o), acc);
        sQ[i*C + o] = acc;
    }
    __syncthreads();

    // ---- Stage J: LayerNorm + global store ----
    {
        int wp = tid >> 5, lid = tid & 31;
        if (wp < PPB) {
            float y0 = sQ[wp*C + lid];
            float y1 = sQ[wp*C + lid + 32];
            float s  = y0 + y1;
            float s2 = y0*y0 + y1*y1;
#pragma unroll
            for (int off = 16; off; off >>= 1) {
                s  += __shfl_xor_sync(0xFFFFFFFFu, s,  off);
                s2 += __shfl_xor_sync(0xFFFFFFFFu, s2, off);
            }
            float mu  = s * (1.f/64.f);
            float var = s2 * (1.f/64.f) - mu*mu;
            float rs  = rsqrtf(var + 1e-5f);
            int g = p0 + wp;
            out[(size_t)g*C + lid]      = (y0 - mu) * rs * lnw[lid]      + lnb[lid];
            out[(size_t)g*C + lid + 32] = (y1 - mu) * rs * lnw[lid + 32] + lnb[lid + 32];
        }
    }
}

// ---------------- launch ----------------
extern "C" void kernel_launch(void* const* d_in, const int* in_sizes, int n_in,
                              void* d_out, int out_size) {
    (void)in_sizes; (void)n_in; (void)out_size;
    const float* cxyz  = (const float*)d_in[0];
    const float* cfeat = (const float*)d_in[1];
    const float* nxyz  = (const float*)d_in[2];
    const float* nfeat = (const float*)d_in[3];
    const float* Wq    = (const float*)d_in[4];
    const float* Wk    = (const float*)d_in[5];
    const float* Wv    = (const float*)d_in[6];
    const float* Wpe1  = (const float*)d_in[7];
    const float* Wpe2  = (const float*)d_in[8];
    const float* Wa1   = (const float*)d_in[9];
    const float* Wa2   = (const float*)d_in[10];
    const float* Wproj = (const float*)d_in[11];
    const float* lnw   = (const float*)d_in[12];
    const float* lnb   = (const float*)d_in[13];

    prep_kernel<<<16, 256>>>(Wq, Wk, Wv, Wpe1, Wpe2, Wa1, Wa2, Wproj);

    size_t smem = 25536 * sizeof(float);   // 102144 B -> 2 blocks/SM
    cudaFuncSetAttribute(lab_kernel, cudaFuncAttributeMaxDynamicSharedMemorySize, (int)smem);
    lab_kernel<<<NPTS/PPB, THREADS, smem>>>(cxyz, cfeat, nxyz, nfeat, lnw, lnb, (float*)d_out);
}

// round 11
// speedup vs baseline: 4.2588x; 1.3729x over previous
#include <cuda_runtime.h>
#include <cstdint>

// Problem constants
#define NPTS   65536      // B*S = 4*16384
#define C      64         // IN_C == OUT_C
#define KNB    16         // neighbors
#define PPB    4          // points per block
#define ROWS   64         // PPB*KNB neighbor rows per block
#define AS     68         // padded row stride
#define HS     20         // padded row stride for H buffer
#define THREADS 256

// ---------------- device-global weight scratch (no allocs) ----------------
__device__ __align__(16) float gWv[4096];      // [c][o]
__device__ __align__(16) float gWpe2[4096];    // [c][o]
__device__ __align__(16) float gWproj_t[4096]; // [c][o]
__device__ __align__(16) float gWa2_t[1024];   // [m][o]
__device__ __align__(16) float gWpe1[192];     // [d][o]
__device__ __align__(16) float gKa1N[1024];    // [i][m] = -(Wa1@Wk)[m][i]
__device__ __align__(16) float gPa1[1024];     // [j][m] =  (Wa1@Wpe2)[m][j]
__device__ __align__(16) float gQa1[1024];     // [i][m] =  (Wa1@Wq)[m][i]

__global__ void prep1_kernel(const float* __restrict__ Wv, const float* __restrict__ Wpe2,
                             const float* __restrict__ Wproj, const float* __restrict__ Wa2,
                             const float* __restrict__ Wpe1) {
    int t = blockIdx.x * blockDim.x + threadIdx.x;
    if (t < 4096) {
        int o = t >> 6, c = t & 63;          // source row-major [o][c]
        gWv    [c*64 + o] = Wv[t];
        gWpe2  [c*64 + o] = Wpe2[t];
        gWproj_t[c*64 + o] = Wproj[t];
    }
    if (t < 1024) {
        int o = t >> 4, m = t & 15;          // Wa2 is [64][16]
        gWa2_t[m*64 + o] = Wa2[t];
    }
    if (t < 192) {
        int o = t / 3, d = t - o*3;          // Wpe1 is [64][3]
        gWpe1[d*64 + o] = Wpe1[t];
    }
}

// fold Wa1 into Wk / Wpe2 / Wq  (tiny 16x64x64 matmuls)
__global__ void prep2_kernel(const float* __restrict__ Wq, const float* __restrict__ Wk,
                             const float* __restrict__ Wpe2, const float* __restrict__ Wa1) {
    int t = blockIdx.x * blockDim.x + threadIdx.x;
    if (t >= 3072) return;
    int sel = t >> 10, idx = t & 1023;
    int i = idx >> 4, m = idx & 15;
    const float* M = (sel == 0) ? Wk : (sel == 1) ? Wpe2 : Wq;
    float acc = 0.f;
#pragma unroll 8
    for (int c = 0; c < 64; ++c) acc += Wa1[m*64 + c] * M[c*64 + i];
    if (sel == 0)      gKa1N[i*16 + m] = -acc;   // negated: h += A @ (-Wka1)
    else if (sel == 1) gPa1[i*16 + m]  = acc;
    else               gQa1[i*16 + m]  = acc;
}

// ---------------- f32x2 packed math helpers ----------------
__device__ __forceinline__ void fma2(uint64_t& d, uint64_t a, uint64_t b) {
    asm("fma.rn.f32x2 %0, %1, %2, %0;" : "+l"(d) : "l"(a), "l"(b));
}
__device__ __forceinline__ uint64_t add2(uint64_t a, uint64_t b) {
    uint64_t d; asm("add.rn.f32x2 %0, %1, %2;" : "=l"(d) : "l"(a), "l"(b)); return d;
}
__device__ __forceinline__ uint64_t pack2(float x, float y) {
    uint64_t d; asm("mov.b64 %0, {%1, %2};" : "=l"(d) : "f"(x), "f"(y)); return d;
}
__device__ __forceinline__ uint64_t dup2(float x) { return pack2(x, x); }
__device__ __forceinline__ void unpack2(uint64_t v, float& x, float& y) {
    asm("mov.b64 {%0, %1}, %2;" : "=f"(x), "=f"(y) : "l"(v));
}
__device__ __forceinline__ uint64_t relu2(uint64_t v) {
    float x, y; unpack2(v, x, y); return pack2(fmaxf(x, 0.f), fmaxf(y, 0.f));
}

// ---------------- main fused kernel ----------------
__global__ void __launch_bounds__(THREADS, 2)
lab_kernel(const float* __restrict__ cxyz, const float* __restrict__ cfeat,
           const float* __restrict__ nxyz, const float* __restrict__ nfeat,
           const float* __restrict__ lnw,  const float* __restrict__ lnb,
           float* __restrict__ out) {
    extern __shared__ float sm[];
    float* sNF   = sm;                 // [64][AS] neigh_feat -> later vpe
    float* sPE   = sNF  + 4352;        // [64][AS] pe_raw -> logits
    float* sH    = sPE  + 4352;        // [64][HS] h
    float* sREL  = sH   + 1280;        // [64][4]  relative xyz
    float* sCF   = sREL + 256;         // [4][64]  center_feat
    float* sQ16  = sCF  + 256;         // [4][16]  qa1 = cf @ (Wa1 Wq)^T
    float* sO    = sQ16 + 64;          // [4][64]  attention output
    float* sY    = sO   + 256;         // [4][64]  y (pre-LN)
    float* sWv   = sY   + 256;         // [64][64] Wv^T
    float* sWpe2 = sWv  + 4096;        // [64][64] Wpe2^T
    float* sKa1  = sWpe2+ 4096;        // [64][16] -(Wa1 Wk)^T
    float* sPa1  = sKa1 + 1024;        // [64][16]  (Wa1 Wpe2)^T
    float* sWa2  = sPa1 + 1024;        // [16][64]
    float* sWpe1 = sWa2 + 1024;        // [3][64]
    // total 22528 floats = 90112 B -> 2 blocks/SM

    const int tid = threadIdx.x;
    const int p0  = blockIdx.x * PPB;
    const int w   = tid >> 5;          // warp -> 8-col block + 2-mid block
    const int l   = tid & 31;          // lane -> rows l and l+32
    const int o0  = w * 8;
    const int m0  = w * 2;
    const int ra  = l;
    const int rb  = l + 32;

    // ---- Stage A: load inputs + stage weights into smem ----
    {
        const float4* nf4 = reinterpret_cast<const float4*>(nfeat + (size_t)p0*KNB*C);
#pragma unroll
        for (int j = tid; j < ROWS*C/4; j += THREADS) {
            float4 v = __ldcs(nf4 + j);
            int e = j*4; int r = e >> 6; int c = e & 63;
            *reinterpret_cast<float4*>(sNF + r*AS + c) = v;
        }
#pragma unroll
        for (int j = tid; j < 1024; j += THREADS) {
            reinterpret_cast<float4*>(sWv)[j]   = reinterpret_cast<const float4*>(gWv)[j];
            reinterpret_cast<float4*>(sWpe2)[j] = reinterpret_cast<const float4*>(gWpe2)[j];
        }
        if (tid < 256) {
            reinterpret_cast<float4*>(sKa1)[tid] = reinterpret_cast<const float4*>(gKa1N)[tid];
            reinterpret_cast<float4*>(sPa1)[tid] = reinterpret_cast<const float4*>(gPa1)[tid];
            reinterpret_cast<float4*>(sWa2)[tid] = reinterpret_cast<const float4*>(gWa2_t)[tid];
        }
        if (tid < 48)
            reinterpret_cast<float4*>(sWpe1)[tid] = reinterpret_cast<const float4*>(gWpe1)[tid];
        if (tid < PPB*C/4) {
            float4 v = __ldcs(reinterpret_cast<const float4*>(cfeat + (size_t)p0*C) + tid);
            int e = tid*4; int i = e >> 6; int c = e & 63;
            *reinterpret_cast<float4*>(sCF + i*C + c) = v;
        }
        if (tid < ROWS) {
            int r = tid, i = r >> 4;
            float cx0 = __ldcs(cxyz + (p0+i)*3 + 0);
            float cx1 = __ldcs(cxyz + (p0+i)*3 + 1);
            float cx2 = __ldcs(cxyz + (p0+i)*3 + 2);
            int nb = (p0*KNB + r)*3;
            sREL[r*4+0] = __ldcs(nxyz + nb + 0) - cx0;
            sREL[r*4+1] = __ldcs(nxyz + nb + 1) - cx1;
            sREL[r*4+2] = __ldcs(nxyz + nb + 2) - cx2;
        }
    }
    __syncthreads();

    // ---- qa1 = cf @ (Wa1 Wq)^T -> sQ16 (64 outputs; folded q projection) ----
    if (tid < 64) {
        int p = tid >> 4, m = tid & 15;
        float acc = 0.f;
#pragma unroll 8
        for (int c = 0; c < 64; ++c) acc = fmaf(sCF[p*C + c], __ldg(gQa1 + c*16 + m), acc);
        sQ16[p*16 + m] = acc;
    }

    // ---- Stage B: pe_raw = relu(rel @ Wpe1^T) -> sPE ----
    {
        uint64_t b0[4], b1[4];
#pragma unroll
        for (int j = 0; j < 4; ++j) { b0[j] = 0ULL; b1[j] = 0ULL; }
#pragma unroll
        for (int d = 0; d < 3; ++d) {
            uint64_t a0 = dup2(sREL[ra*4 + d]);
            uint64_t a1 = dup2(sREL[rb*4 + d]);
            const float* wr = sWpe1 + d*64 + o0;
            ulonglong2 w01 = *reinterpret_cast<const ulonglong2*>(wr);
            ulonglong2 w23 = *reinterpret_cast<const ulonglong2*>(wr + 4);
            fma2(b0[0], a0, w01.x); fma2(b0[1], a0, w01.y);
            fma2(b0[2], a0, w23.x); fma2(b0[3], a0, w23.y);
            fma2(b1[0], a1, w01.x); fma2(b1[1], a1, w01.y);
            fma2(b1[2], a1, w23.x); fma2(b1[3], a1, w23.y);
        }
#pragma unroll
        for (int j = 0; j < 4; ++j) { b0[j] = relu2(b0[j]); b1[j] = relu2(b1[j]); }
        *reinterpret_cast<ulonglong2*>(sPE + ra*AS + o0)     = make_ulonglong2(b0[0], b0[1]);
        *reinterpret_cast<ulonglong2*>(sPE + ra*AS + o0 + 4) = make_ulonglong2(b0[2], b0[3]);
        *reinterpret_cast<ulonglong2*>(sPE + rb*AS + o0)     = make_ulonglong2(b1[0], b1[1]);
        *reinterpret_cast<ulonglong2*>(sPE + rb*AS + o0 + 4) = make_ulonglong2(b1[2], b1[3]);
    }
    __syncthreads();   // (1) pe_raw + qa1 visible

    // ---- Stage C: pe = pe_raw @ Wpe2^T (regs) ; hpe = pe_raw @ Pa1 (regs) ----
    uint64_t pc[2][4];
    uint64_t hpe[2];
    {
#pragma unroll
        for (int j = 0; j < 4; ++j) { pc[0][j] = 0ULL; pc[1][j] = 0ULL; }
        hpe[0] = 0ULL; hpe[1] = 0ULL;
#pragma unroll 4
        for (int c = 0; c < 64; c += 4) {
            float4 A0 = *reinterpret_cast<const float4*>(sPE + ra*AS + c);
            float4 A1 = *reinterpret_cast<const float4*>(sPE + rb*AS + c);
            float a0v[4] = {A0.x, A0.y, A0.z, A0.w};
            float a1v[4] = {A1.x, A1.y, A1.z, A1.w};
#pragma unroll
            for (int u = 0; u < 4; ++u) {
                uint64_t a0 = dup2(a0v[u]);
                uint64_t a1 = dup2(a1v[u]);
                const float* wr = sWpe2 + (c+u)*64 + o0;
                ulonglong2 w01 = *reinterpret_cast<const ulonglong2*>(wr);
                ulonglong2 w23 = *reinterpret_cast<const ulonglong2*>(wr + 4);
                fma2(pc[0][0], a0, w01.x); fma2(pc[0][1], a0, w01.y);
                fma2(pc[0][2], a0, w23.x); fma2(pc[0][3], a0, w23.y);
                fma2(pc[1][0], a1, w01.x); fma2(pc[1][1], a1, w01.y);
                fma2(pc[1][2], a1, w23.x); fma2(pc[1][3], a1, w23.y);
                uint64_t pw = *reinterpret_cast<const uint64_t*>(sPa1 + (c+u)*16 + m0);
                fma2(hpe[0], a0, pw);
                fma2(hpe[1], a1, pw);
            }
        }
    }

    // ---- Stage D: v = A@Wv^T ; hk = A@(-Wka1) ; vpe = v+pe -> sNF ; h -> sH ----
    {
        uint64_t av[2][4];
        uint64_t hk[2];
#pragma unroll
        for (int j = 0; j < 4; ++j) { av[0][j] = pc[0][j]; av[1][j] = pc[1][j]; }
        const int pa = ra >> 4, pb = rb >> 4;
        hk[0] = add2(*reinterpret_cast<const uint64_t*>(sQ16 + pa*16 + m0), hpe[0]);
        hk[1] = add2(*reinterpret_cast<const uint64_t*>(sQ16 + pb*16 + m0), hpe[1]);
#pragma unroll 4
        for (int c = 0; c < 64; c += 4) {
            float4 A0 = *reinterpret_cast<const float4*>(sNF + ra*AS + c);
            float4 A1 = *reinterpret_cast<const float4*>(sNF + rb*AS + c);
            float a0v[4] = {A0.x, A0.y, A0.z, A0.w};
            float a1v[4] = {A1.x, A1.y, A1.z, A1.w};
#pragma unroll
            for (int u = 0; u < 4; ++u) {
                uint64_t a0 = dup2(a0v[u]);
                uint64_t a1 = dup2(a1v[u]);
                const float* wr = sWv + (c+u)*64 + o0;
                ulonglong2 w01 = *reinterpret_cast<const ulonglong2*>(wr);
                ulonglong2 w23 = *reinterpret_cast<const ulonglong2*>(wr + 4);
                fma2(av[0][0], a0, w01.x); fma2(av[0][1], a0, w01.y);
                fma2(av[0][2], a0, w23.x); fma2(av[0][3], a0, w23.y);
                fma2(av[1][0], a1, w01.x); fma2(av[1][1], a1, w01.y);
                fma2(av[1][2], a1, w23.x); fma2(av[1][3], a1, w23.y);
                uint64_t kw = *reinterpret_cast<const uint64_t*>(sKa1 + (c+u)*16 + m0);
                fma2(hk[0], a0, kw);
                fma2(hk[1], a1, kw);
            }
        }
        __syncthreads();   // (2) all reads of sNF (neigh_feat) and sPE (pe_raw) done
        *reinterpret_cast<ulonglong2*>(sNF + ra*AS + o0)     = make_ulonglong2(av[0][0], av[0][1]);
        *reinterpret_cast<ulonglong2*>(sNF + ra*AS + o0 + 4) = make_ulonglong2(av[0][2], av[0][3]);
        *reinterpret_cast<ulonglong2*>(sNF + rb*AS + o0)     = make_ulonglong2(av[1][0], av[1][1]);
        *reinterpret_cast<ulonglong2*>(sNF + rb*AS + o0 + 4) = make_ulonglong2(av[1][2], av[1][3]);
        *reinterpret_cast<uint64_t*>(sH + ra*HS + m0) = relu2(hk[0]);
        *reinterpret_cast<uint64_t*>(sH + rb*HS + m0) = relu2(hk[1]);
    }
    __syncthreads();   // (3) vpe and h visible

    // ---- Stage G: logits = h @ Wa2^T -> sPE ----
    {
        uint64_t g[2][4];
#pragma unroll
        for (int j = 0; j < 4; ++j) { g[0][j] = 0ULL; g[1][j] = 0ULL; }
#pragma unroll
        for (int m = 0; m < 16; m += 4) {
            float4 H0 = *reinterpret_cast<const float4*>(sH + ra*HS + m);
            float4 H1 = *reinterpret_cast<const float4*>(sH + rb*HS + m);
            float h0v[4] = {H0.x, H0.y, H0.z, H0.w};
            float h1v[4] = {H1.x, H1.y, H1.z, H1.w};
#pragma unroll
            for (int u = 0; u < 4; ++u) {
                uint64_t a0 = dup2(h0v[u]);
                uint64_t a1 = dup2(h1v[u]);
                const float* wr = sWa2 + (m+u)*64 + o0;
                ulonglong2 w01 = *reinterpret_cast<const ulonglong2*>(wr);
                ulonglong2 w23 = *reinterpret_cast<const ulonglong2*>(wr + 4);
                fma2(g[0][0], a0, w01.x); fma2(g[0][1], a0, w01.y);
                fma2(g[0][2], a0, w23.x); fma2(g[0][3], a0, w23.y);
                fma2(g[1][0], a1, w01.x); fma2(g[1][1], a1, w01.y);
                fma2(g[1][2], a1, w23.x); fma2(g[1][3], a1, w23.y);
            }
        }
        *reinterpret_cast<ulonglong2*>(sPE + ra*AS + o0)     = make_ulonglong2(g[0][0], g[0][1]);
        *reinterpret_cast<ulonglong2*>(sPE + ra*AS + o0 + 4) = make_ulonglong2(g[0][2], g[0][3]);
        *reinterpret_cast<ulonglong2*>(sPE + rb*AS + o0)     = make_ulonglong2(g[1][0], g[1][1]);
        *reinterpret_cast<ulonglong2*>(sPE + rb*AS + o0 + 4) = make_ulonglong2(g[1][2], g[1][3]);
    }
    __syncthreads();   // (4) logits visible

    // ---- Stage H: softmax over K + weighted sum of vpe -> sO ----
    {
        int i = tid >> 6, o = tid & 63;
        int rbase = i * KNB;
        float wv[KNB];
        float mx = -1e30f;
#pragma unroll
        for (int k = 0; k < KNB; ++k) {
            wv[k] = sPE[(rbase+k)*AS + o];
            mx = fmaxf(mx, wv[k]);
        }
        float sum = 0.f;
#pragma unroll
        for (int k = 0; k < KNB; ++k) { wv[k] = __expf(wv[k] - mx); sum += wv[k]; }
        float inv = 1.f / sum;
        float acc = 0.f;
#pragma unroll
        for (int k = 0; k < KNB; ++k) acc = fmaf(wv[k], sNF[(rbase+k)*AS + o], acc);
        sO[i*C + o] = acc * inv;
    }
    __syncthreads();

    // ---- Stage I: proj + residual -> sY ----
    {
        int i = tid >> 6, o = tid & 63;
        float acc = sCF[i*C + o];
#pragma unroll 8
        for (int c = 0; c < 64; ++c) acc = fmaf(sO[i*C + c], __ldg(gWproj_t + c*64 + o), acc);
        sY[i*C + o] = acc;
    }
    __syncthreads();

    // ---- Stage J: LayerNorm + global store ----
    {
        int wp = tid >> 5, lid = tid & 31;
        if (wp < PPB) {
            float y0 = sY[wp*C + lid];
            float y1 = sY[wp*C + lid + 32];
            float s  = y0 + y1;
            float s2 = y0*y0 + y1*y1;
#pragma unroll
            for (int off = 16; off; off >>= 1) {
                s  += __shfl_xor_sync(0xFFFFFFFFu, s,  off);
                s2 += __shfl_xor_sync(0xFFFFFFFFu, s2, off);
            }
            float mu  = s * (1.f/64.f);
            float var = s2 * (1.f/64.f) - mu*mu;
            float rs  = rsqrtf(var + 1e-5f);
            int g = p0 + wp;
            out[(size_t)g*C + lid]      = (y0 - mu) * rs * lnw[lid]      + lnb[lid];
            out[(size_t)g*C + lid + 32] = (y1 - mu) * rs * lnw[lid + 32] + lnb[lid + 32];
        }
    }
}

// ---------------- launch ----------------
extern "C" void kernel_launch(void* const* d_in, const int* in_sizes, int n_in,
                              void* d_out, int out_size) {
    (void)in_sizes; (void)n_in; (void)out_size;
    const float* cxyz  = (const float*)d_in[0];
    const float* cfeat = (const float*)d_in[1];
    const float* nxyz  = (const float*)d_in[2];
    const float* nfeat = (const float*)d_in[3];
    const float* Wq    = (const float*)d_in[4];
    const float* Wk    = (const float*)d_in[5];
    const float* Wv    = (const float*)d_in[6];
    const float* Wpe1  = (const float*)d_in[7];
    const float* Wpe2  = (const float*)d_in[8];
    const float* Wa1   = (const float*)d_in[9];
    const float* Wa2   = (const float*)d_in[10];
    const float* Wproj = (const float*)d_in[11];
    const float* lnw   = (const float*)d_in[12];
    const float* lnb   = (const float*)d_in[13];

    prep1_kernel<<<16, 256>>>(Wv, Wpe2, Wproj, Wa2, Wpe1);
    prep2_kernel<<<12, 256>>>(Wq, Wk, Wpe2, Wa1);

    size_t smem = 22528 * sizeof(float);   // 90112 B -> 2 blocks/SM
    cudaFuncSetAttribute(lab_kernel, cudaFuncAttributeMaxDynamicSharedMemorySize, (int)smem);
    lab_kernel<<<NPTS/PPB, THREADS, smem>>>(cxyz, cfeat, nxyz, nfeat, lnw, lnb, (float*)d_out);
}